// round 2
// baseline (speedup 1.0000x reference)
#include <cuda_runtime.h>
#include <math.h>

#define BATCH 4
#define TLEN  4096
#define DM    1024
#define HEADS 16
#define NSK   6
#define SEQ   (BATCH*HEADS)     // 64
#define MROWS (BATCH*TLEN)      // 16384
#define CL    64                // scan chunk length
#define NCH   (TLEN/CL)         // 64 chunks per sequence

// ---------------- scratch (static device globals; no runtime alloc) -------
__device__ __align__(16) float g_skew[SEQ*TLEN*NSK];   //  6.3 MB, seq-major
__device__ __align__(16) float g_v   [SEQ*TLEN*4];     //  4.2 MB, seq-major
__device__ __align__(16) float g_O   [SEQ*TLEN*16];    // 16.8 MB rotation mats
__device__ __align__(16) float g_CT  [SEQ*NCH*16];     // chunk totals
__device__ __align__(16) float g_PF  [SEQ*NCH*16];     // chunk prefixes
__device__ __align__(16) float g_rot [MROWS*64];       //  4.2 MB, gemm layout

// 4x4 matmul: C = A @ B (row-major, 16 floats each)
__device__ __forceinline__ void mm4(const float* __restrict__ A,
                                    const float* __restrict__ Bm,
                                    float* __restrict__ C) {
#pragma unroll
    for (int i = 0; i < 4; i++) {
#pragma unroll
        for (int j = 0; j < 4; j++) {
            C[i*4+j] = A[i*4+0]*Bm[0*4+j] + A[i*4+1]*Bm[1*4+j]
                     + A[i*4+2]*Bm[2*4+j] + A[i*4+3]*Bm[3*4+j];
        }
    }
}

// ======================= K1: G = x @ [W_skew | W_v] =======================
// M=16384, K=1024, N=160 (96 skew cols + 64 v cols). fp32.
// Block: 64 rows x 160 cols, 256 threads, micro-tile 4x10.
__global__ __launch_bounds__(256) void k1_gemm_in(
    const float* __restrict__ x,
    const float* __restrict__ Wsk,
    const float* __restrict__ Wv)
{
    __shared__ float sx[64][17];     // [m][k], padded
    __shared__ float sw[16][160];    // [k][n]

    const int tid = threadIdx.x;
    const int tx  = tid & 15;        // col group (16)
    const int ty  = tid >> 4;        // row group (16)
    const int m0  = blockIdx.x * 64;

    float acc[4][10];
#pragma unroll
    for (int i = 0; i < 4; i++)
#pragma unroll
        for (int j = 0; j < 10; j++) acc[i][j] = 0.f;

    const int li = tid >> 2;            // 0..63
    const int lk = (tid & 3) << 2;      // 0,4,8,12

    for (int k0 = 0; k0 < DM; k0 += 16) {
        float4 xv = *(const float4*)(x + (size_t)(m0 + li)*DM + k0 + lk);
        sx[li][lk+0] = xv.x; sx[li][lk+1] = xv.y;
        sx[li][lk+2] = xv.z; sx[li][lk+3] = xv.w;
#pragma unroll
        for (int j = 0; j < 10; j++) {
            int idx = tid + j*256;            // 0..2559
            int kk  = idx / 160;
            int n   = idx - kk*160;
            float w = (n < 96) ? Wsk[(size_t)(k0+kk)*96 + n]
                               : Wv [(size_t)(k0+kk)*64 + (n - 96)];
            sw[kk][n] = w;
        }
        __syncthreads();
#pragma unroll
        for (int k = 0; k < 16; k++) {
            float a0 = sx[ty*4+0][k], a1 = sx[ty*4+1][k];
            float a2 = sx[ty*4+2][k], a3 = sx[ty*4+3][k];
#pragma unroll
            for (int j = 0; j < 10; j++) {
                float bv = sw[k][tx + j*16];
                acc[0][j] += a0*bv; acc[1][j] += a1*bv;
                acc[2][j] += a2*bv; acc[3][j] += a3*bv;
            }
        }
        __syncthreads();
    }

    // scatter to seq-major layouts
#pragma unroll
    for (int ii = 0; ii < 4; ii++) {
        int m  = m0 + ty*4 + ii;
        int bb = m >> 12;              // / TLEN
        int t  = m & (TLEN - 1);
#pragma unroll
        for (int j = 0; j < 10; j++) {
            int n = tx + j*16;
            float vv = acc[ii][j];
            if (n < 96) {
                int h = n / 6, kk = n - h*6;
                g_skew[((size_t)(bb*HEADS + h)*TLEN + t)*NSK + kk] = vv;
            } else {
                int i2 = n - 96;
                int h = i2 >> 2, cc = i2 & 3;
                g_v[((size_t)(bb*HEADS + h)*TLEN + t)*4 + cc] = vv;
            }
        }
    }
}

// ======================= K2: O_t = expm(skew) =============================
// Scaling-and-squaring + order-9 Taylor (Horner). ||Y|| <= 0.5 => rem ~3e-10.
__global__ __launch_bounds__(256) void k2_expm()
{
    int u = blockIdx.x * 256 + threadIdx.x;     // 0 .. SEQ*TLEN-1
    const float* s = g_skew + (size_t)u * NSK;
    float a = s[0], b = s[1], c = s[2], d = s[3], e = s[4], f = s[5];

    float nrm = sqrtf(2.f*(a*a + b*b + c*c + d*d + e*e + f*f));
    int sh = 0;
    if (nrm > 0.5f) {
        sh = (int)ceilf(log2f(nrm)) + 1;
        if (sh < 1) sh = 1;
    }
    float sc = exp2f(-(float)sh);
    a *= sc; b *= sc; c *= sc; d *= sc; e *= sc; f *= sc;

    float Y[16] = { 0,  a,  b,  c,
                   -a,  0,  d,  e,
                   -b, -d,  0,  f,
                   -c, -e, -f,  0};
    float Mt[16];
#pragma unroll
    for (int i = 0; i < 16; i++) Mt[i] = Y[i] * (1.f/9.f);
    Mt[0] += 1.f; Mt[5] += 1.f; Mt[10] += 1.f; Mt[15] += 1.f;
#pragma unroll
    for (int j = 8; j >= 1; j--) {
        float Tt[16];
        mm4(Y, Mt, Tt);
        float inv = 1.f / (float)j;
#pragma unroll
        for (int i = 0; i < 16; i++) Mt[i] = Tt[i] * inv;
        Mt[0] += 1.f; Mt[5] += 1.f; Mt[10] += 1.f; Mt[15] += 1.f;
    }
    for (int q = 0; q < sh; q++) {
        float Tt[16];
        mm4(Mt, Mt, Tt);
#pragma unroll
        for (int i = 0; i < 16; i++) Mt[i] = Tt[i];
    }
    float4* o = (float4*)(g_O + (size_t)u * 16);
    o[0] = make_float4(Mt[0],  Mt[1],  Mt[2],  Mt[3]);
    o[1] = make_float4(Mt[4],  Mt[5],  Mt[6],  Mt[7]);
    o[2] = make_float4(Mt[8],  Mt[9],  Mt[10], Mt[11]);
    o[3] = make_float4(Mt[12], Mt[13], Mt[14], Mt[15]);
}

// ======================= K3: per-chunk total products =====================
// One thread per (seq, chunk): CT = O_last @ ... @ O_first
__global__ __launch_bounds__(256) void k3_chunk()
{
    int id  = blockIdx.x * 256 + threadIdx.x;   // SEQ*NCH = 4096
    int seq = id >> 6;                          // / NCH
    int c   = id & (NCH - 1);
    const float4* __restrict__ Op =
        (const float4*)(g_O + ((size_t)seq*TLEN + c*CL)*16);

    float R[16];
    {
        float4 a0 = Op[0], a1 = Op[1], a2 = Op[2], a3 = Op[3];
        R[0]=a0.x; R[1]=a0.y; R[2]=a0.z; R[3]=a0.w;
        R[4]=a1.x; R[5]=a1.y; R[6]=a1.z; R[7]=a1.w;
        R[8]=a2.x; R[9]=a2.y; R[10]=a2.z; R[11]=a2.w;
        R[12]=a3.x; R[13]=a3.y; R[14]=a3.z; R[15]=a3.w;
    }
#pragma unroll 4
    for (int t = 1; t < CL; t++) {
        float4 a0 = Op[t*4+0], a1 = Op[t*4+1], a2 = Op[t*4+2], a3 = Op[t*4+3];
        float O[16] = {a0.x,a0.y,a0.z,a0.w, a1.x,a1.y,a1.z,a1.w,
                       a2.x,a2.y,a2.z,a2.w, a3.x,a3.y,a3.z,a3.w};
        float Nn[16];
        mm4(O, R, Nn);
#pragma unroll
        for (int i = 0; i < 16; i++) R[i] = Nn[i];
    }
    float4* ct = (float4*)(g_CT + (size_t)id * 16);
    ct[0] = make_float4(R[0],R[1],R[2],R[3]);
    ct[1] = make_float4(R[4],R[5],R[6],R[7]);
    ct[2] = make_float4(R[8],R[9],R[10],R[11]);
    ct[3] = make_float4(R[12],R[13],R[14],R[15]);
}

// ======================= K4: cross-chunk exclusive prefix =================
// One thread per sequence: PF[c] = CT[c-1] @ ... @ CT[0], PF[0] = I
__global__ void k4_prefix()
{
    int seq = blockIdx.x * 32 + threadIdx.x;
    if (seq >= SEQ) return;
    float P[16] = {1,0,0,0, 0,1,0,0, 0,0,1,0, 0,0,0,1};
    for (int c = 0; c < NCH; c++) {
        float4* pf = (float4*)(g_PF + ((size_t)seq*NCH + c)*16);
        pf[0] = make_float4(P[0],P[1],P[2],P[3]);
        pf[1] = make_float4(P[4],P[5],P[6],P[7]);
        pf[2] = make_float4(P[8],P[9],P[10],P[11]);
        pf[3] = make_float4(P[12],P[13],P[14],P[15]);
        const float4* ct = (const float4*)(g_CT + ((size_t)seq*NCH + c)*16);
        float4 a0 = ct[0], a1 = ct[1], a2 = ct[2], a3 = ct[3];
        float C[16] = {a0.x,a0.y,a0.z,a0.w, a1.x,a1.y,a1.z,a1.w,
                       a2.x,a2.y,a2.z,a2.w, a3.x,a3.y,a3.z,a3.w};
        float Nn[16];
        mm4(C, P, Nn);
#pragma unroll
        for (int i = 0; i < 16; i++) P[i] = Nn[i];
    }
}

// ======================= K5: apply scan + rotate v ========================
// R starts at chunk prefix; R = O_t @ R gives states[t]; rot = R @ v[t]
__global__ __launch_bounds__(256) void k5_apply()
{
    int id  = blockIdx.x * 256 + threadIdx.x;   // 4096
    int seq = id >> 6;
    int c   = id & (NCH - 1);
    int bb  = seq >> 4;            // / HEADS
    int h   = seq & (HEADS - 1);

    float R[16];
    {
        const float4* pf = (const float4*)(g_PF + (size_t)id * 16);
        float4 a0 = pf[0], a1 = pf[1], a2 = pf[2], a3 = pf[3];
        R[0]=a0.x; R[1]=a0.y; R[2]=a0.z; R[3]=a0.w;
        R[4]=a1.x; R[5]=a1.y; R[6]=a1.z; R[7]=a1.w;
        R[8]=a2.x; R[9]=a2.y; R[10]=a2.z; R[11]=a2.w;
        R[12]=a3.x; R[13]=a3.y; R[14]=a3.z; R[15]=a3.w;
    }
    const float4* __restrict__ Op =
        (const float4*)(g_O + ((size_t)seq*TLEN + c*CL)*16);
    const float4* __restrict__ Vp =
        (const float4*)(g_v + ((size_t)seq*TLEN + c*CL)*4);
    const int trow0 = bb*TLEN + c*CL;

#pragma unroll 4
    for (int t = 0; t < CL; t++) {
        float4 a0 = Op[t*4+0], a1 = Op[t*4+1], a2 = Op[t*4+2], a3 = Op[t*4+3];
        float4 vv = Vp[t];
        float O[16] = {a0.x,a0.y,a0.z,a0.w, a1.x,a1.y,a1.z,a1.w,
                       a2.x,a2.y,a2.z,a2.w, a3.x,a3.y,a3.z,a3.w};
        float Nn[16];
        mm4(O, R, Nn);
#pragma unroll
        for (int i = 0; i < 16; i++) R[i] = Nn[i];
        float r0 = R[0]*vv.x  + R[1]*vv.y  + R[2]*vv.z  + R[3]*vv.w;
        float r1 = R[4]*vv.x  + R[5]*vv.y  + R[6]*vv.z  + R[7]*vv.w;
        float r2 = R[8]*vv.x  + R[9]*vv.y  + R[10]*vv.z + R[11]*vv.w;
        float r3 = R[12]*vv.x + R[13]*vv.y + R[14]*vv.z + R[15]*vv.w;
        *(float4*)(g_rot + (size_t)(trow0 + t)*64 + h*4) = make_float4(r0, r1, r2, r3);
    }
}

// ======================= K6: out = rot @ W_o ==============================
// M=16384, K=64, N=1024. Block 64x128, 256 threads, micro 8x4. K fully in smem.
__global__ __launch_bounds__(256) void k6_gemm_out(
    const float* __restrict__ Wo, float* __restrict__ out)
{
    __shared__ float sa[64][64];     // rot tile  (16 KB)
    __shared__ float sw[64][128];    // W_o tile  (32 KB)

    const int tid = threadIdx.x;
    const int tx  = tid & 31;
    const int ty  = tid >> 5;
    const int m0  = blockIdx.x * 64;
    const int n0  = blockIdx.y * 128;

#pragma unroll
    for (int j = 0; j < 4; j++) {
        int idx4 = tid + j*256;                 // 1024 float4s
        int row = idx4 >> 4, k4 = idx4 & 15;
        *(float4*)&sa[row][k4*4] =
            ((const float4*)(g_rot + (size_t)(m0 + row)*64))[k4];
    }
#pragma unroll
    for (int j = 0; j < 8; j++) {
        int idx4 = tid + j*256;                 // 2048 float4s
        int row = idx4 >> 5, n4 = idx4 & 31;
        *(float4*)&sw[row][n4*4] =
            *(const float4*)(Wo + (size_t)row*DM + n0 + n4*4);
    }
    __syncthreads();

    float acc[8][4];
#pragma unroll
    for (int i = 0; i < 8; i++)
#pragma unroll
        for (int j = 0; j < 4; j++) acc[i][j] = 0.f;

#pragma unroll 8
    for (int k = 0; k < 64; k++) {
        float a[8];
#pragma unroll
        for (int ii = 0; ii < 8; ii++) a[ii] = sa[ty*8 + ii][k];
#pragma unroll
        for (int jj = 0; jj < 4; jj++) {
            float bv = sw[k][tx + jj*32];
#pragma unroll
            for (int ii = 0; ii < 8; ii++) acc[ii][jj] += a[ii]*bv;
        }
    }

#pragma unroll
    for (int ii = 0; ii < 8; ii++) {
        size_t rowoff = (size_t)(m0 + ty*8 + ii)*DM + n0;
#pragma unroll
        for (int jj = 0; jj < 4; jj++)
            out[rowoff + tx + jj*32] = acc[ii][jj];
    }
}

// =========================================================================
extern "C" void kernel_launch(void* const* d_in, const int* in_sizes, int n_in,
                              void* d_out, int out_size)
{
    const float* x   = (const float*)d_in[0];
    const float* Wsk = (const float*)d_in[1];
    const float* Wv  = (const float*)d_in[2];
    const float* Wo  = (const float*)d_in[3];
    float* out = (float*)d_out;

    k1_gemm_in<<<MROWS/64, 256>>>(x, Wsk, Wv);          // 256 blocks
    k2_expm  <<<SEQ*TLEN/256, 256>>>();                  // 1024 blocks
    k3_chunk <<<SEQ*NCH/256, 256>>>();                   // 16 blocks
    k4_prefix<<<SEQ/32, 32>>>();                         // 2 blocks
    k5_apply <<<SEQ*NCH/256, 256>>>();                   // 16 blocks
    k6_gemm_out<<<dim3(MROWS/64, DM/128), 256>>>(Wo, out);
}

// round 5
// speedup vs baseline: 1.2709x; 1.2709x over previous
#include <cuda_runtime.h>
#include <math.h>

#define BATCH 4
#define TLEN  4096
#define DM    1024
#define HEADS 16
#define NSK   6
#define SEQ   (BATCH*HEADS)     // 64
#define MROWS (BATCH*TLEN)      // 16384
#define CL    8                 // scan chunk length
#define NCH   (TLEN/CL)         // 512 chunks per sequence

// ---------------- scratch (static device globals; no runtime alloc) -------
__device__ __align__(16) float g_skew[SEQ*TLEN*NSK];   //  6.3 MB, seq-major
__device__ __align__(16) float g_v   [SEQ*TLEN*4];     //  4.2 MB, seq-major
__device__ __align__(16) float g_O   [SEQ*TLEN*16];    // 16.8 MB rotation mats
__device__ __align__(16) float g_rot [MROWS*64];       //  4.2 MB, gemm layout

// 4x4 matmul: C = A @ B (row-major, 16 floats each)
__device__ __forceinline__ void mm4(const float* __restrict__ A,
                                    const float* __restrict__ Bm,
                                    float* __restrict__ C) {
#pragma unroll
    for (int i = 0; i < 4; i++) {
#pragma unroll
        for (int j = 0; j < 4; j++) {
            C[i*4+j] = A[i*4+0]*Bm[0*4+j] + A[i*4+1]*Bm[1*4+j]
                     + A[i*4+2]*Bm[2*4+j] + A[i*4+3]*Bm[3*4+j];
        }
    }
}

// ======================= K1: G = x @ [W_skew | W_v] =======================
// M=16384, K=1024, N=160 (96 skew cols + 64 v cols). fp32.
// Block: 64 rows x 160 cols, 256 threads, micro-tile 4x10.
__global__ __launch_bounds__(256) void k1_gemm_in(
    const float* __restrict__ x,
    const float* __restrict__ Wsk,
    const float* __restrict__ Wv)
{
    __shared__ float sx[64][17];     // [m][k], padded
    __shared__ float sw[16][160];    // [k][n]

    const int tid = threadIdx.x;
    const int tx  = tid & 15;        // col group (16)
    const int ty  = tid >> 4;        // row group (16)
    const int m0  = blockIdx.x * 64;

    float acc[4][10];
#pragma unroll
    for (int i = 0; i < 4; i++)
#pragma unroll
        for (int j = 0; j < 10; j++) acc[i][j] = 0.f;

    const int li = tid >> 2;            // 0..63
    const int lk = (tid & 3) << 2;      // 0,4,8,12

    for (int k0 = 0; k0 < DM; k0 += 16) {
        float4 xv = *(const float4*)(x + (size_t)(m0 + li)*DM + k0 + lk);
        sx[li][lk+0] = xv.x; sx[li][lk+1] = xv.y;
        sx[li][lk+2] = xv.z; sx[li][lk+3] = xv.w;
#pragma unroll
        for (int j = 0; j < 10; j++) {
            int idx = tid + j*256;            // 0..2559
            int kk  = idx / 160;
            int n   = idx - kk*160;
            float w = (n < 96) ? Wsk[(size_t)(k0+kk)*96 + n]
                               : Wv [(size_t)(k0+kk)*64 + (n - 96)];
            sw[kk][n] = w;
        }
        __syncthreads();
#pragma unroll
        for (int k = 0; k < 16; k++) {
            float a0 = sx[ty*4+0][k], a1 = sx[ty*4+1][k];
            float a2 = sx[ty*4+2][k], a3 = sx[ty*4+3][k];
#pragma unroll
            for (int j = 0; j < 10; j++) {
                float bv = sw[k][tx + j*16];
                acc[0][j] += a0*bv; acc[1][j] += a1*bv;
                acc[2][j] += a2*bv; acc[3][j] += a3*bv;
            }
        }
        __syncthreads();
    }

    // scatter to seq-major layouts
#pragma unroll
    for (int ii = 0; ii < 4; ii++) {
        int m  = m0 + ty*4 + ii;
        int bb = m >> 12;              // / TLEN
        int t  = m & (TLEN - 1);
#pragma unroll
        for (int j = 0; j < 10; j++) {
            int n = tx + j*16;
            float vv = acc[ii][j];
            if (n < 96) {
                int h = n / 6, kk = n - h*6;
                g_skew[((size_t)(bb*HEADS + h)*TLEN + t)*NSK + kk] = vv;
            } else {
                int i2 = n - 96;
                int h = i2 >> 2, cc = i2 & 3;
                g_v[((size_t)(bb*HEADS + h)*TLEN + t)*4 + cc] = vv;
            }
        }
    }
}

// ======================= K2: O_t = expm(skew) =============================
// Scaling-and-squaring + order-9 Taylor (Horner). ||Y|| <= 0.5 => rem ~3e-10.
__global__ __launch_bounds__(256) void k2_expm()
{
    int u = blockIdx.x * 256 + threadIdx.x;     // 0 .. SEQ*TLEN-1
    const float* s = g_skew + (size_t)u * NSK;
    float a = s[0], b = s[1], c = s[2], d = s[3], e = s[4], f = s[5];

    float nrm = sqrtf(2.f*(a*a + b*b + c*c + d*d + e*e + f*f));
    int sh = 0;
    if (nrm > 0.5f) {
        sh = (int)ceilf(log2f(nrm)) + 1;
        if (sh < 1) sh = 1;
    }
    float sc = exp2f(-(float)sh);
    a *= sc; b *= sc; c *= sc; d *= sc; e *= sc; f *= sc;

    float Y[16] = { 0,  a,  b,  c,
                   -a,  0,  d,  e,
                   -b, -d,  0,  f,
                   -c, -e, -f,  0};
    float Mt[16];
#pragma unroll
    for (int i = 0; i < 16; i++) Mt[i] = Y[i] * (1.f/9.f);
    Mt[0] += 1.f; Mt[5] += 1.f; Mt[10] += 1.f; Mt[15] += 1.f;
#pragma unroll
    for (int j = 8; j >= 1; j--) {
        float Tt[16];
        mm4(Y, Mt, Tt);
        float inv = 1.f / (float)j;
#pragma unroll
        for (int i = 0; i < 16; i++) Mt[i] = Tt[i] * inv;
        Mt[0] += 1.f; Mt[5] += 1.f; Mt[10] += 1.f; Mt[15] += 1.f;
    }
    for (int q = 0; q < sh; q++) {
        float Tt[16];
        mm4(Mt, Mt, Tt);
#pragma unroll
        for (int i = 0; i < 16; i++) Mt[i] = Tt[i];
    }
    float4* o = (float4*)(g_O + (size_t)u * 16);
    o[0] = make_float4(Mt[0],  Mt[1],  Mt[2],  Mt[3]);
    o[1] = make_float4(Mt[4],  Mt[5],  Mt[6],  Mt[7]);
    o[2] = make_float4(Mt[8],  Mt[9],  Mt[10], Mt[11]);
    o[3] = make_float4(Mt[12], Mt[13], Mt[14], Mt[15]);
}

// =========== K345: fused chunk product + Kogge-Stone scan + apply =========
// 64 blocks (one per sequence) x 512 threads (one per chunk, CL=8).
// Pure CUDA: no mbarriers, no async ops; all __syncthreads unconditional.
__global__ __launch_bounds__(512) void k345_scan()
{
    __shared__ float sP[NCH*17];
    const int seq = blockIdx.x;
    const int c   = threadIdx.x;            // chunk id 0..511
    const float4* __restrict__ Op =
        (const float4*)(g_O + ((size_t)seq*TLEN + c*CL)*16);

    // phase A: chunk product  R = O_{last} @ ... @ O_{first}
    float R[16];
    {
        float4 a0 = Op[0], a1 = Op[1], a2 = Op[2], a3 = Op[3];
        R[0]=a0.x; R[1]=a0.y; R[2]=a0.z; R[3]=a0.w;
        R[4]=a1.x; R[5]=a1.y; R[6]=a1.z; R[7]=a1.w;
        R[8]=a2.x; R[9]=a2.y; R[10]=a2.z; R[11]=a2.w;
        R[12]=a3.x; R[13]=a3.y; R[14]=a3.z; R[15]=a3.w;
    }
#pragma unroll
    for (int t = 1; t < CL; t++) {
        float4 a0 = Op[t*4+0], a1 = Op[t*4+1], a2 = Op[t*4+2], a3 = Op[t*4+3];
        float O[16] = {a0.x,a0.y,a0.z,a0.w, a1.x,a1.y,a1.z,a1.w,
                       a2.x,a2.y,a2.z,a2.w, a3.x,a3.y,a3.z,a3.w};
        float Nn[16];
        mm4(O, R, Nn);
#pragma unroll
        for (int i = 0; i < 16; i++) R[i] = Nn[i];
    }

    // phase B: Kogge-Stone inclusive scan over 512 chunks (9 steps)
    for (int d = 1; d < NCH; d <<= 1) {
#pragma unroll
        for (int i = 0; i < 16; i++) sP[c*17 + i] = R[i];
        __syncthreads();
        if (c >= d) {
            float Q[16];
#pragma unroll
            for (int i = 0; i < 16; i++) Q[i] = sP[(c-d)*17 + i];
            float Nn[16];
            mm4(R, Q, Nn);                     // newer-window @ older-window
#pragma unroll
            for (int i = 0; i < 16; i++) R[i] = Nn[i];
        }
        __syncthreads();
    }
    // convert to exclusive prefix
#pragma unroll
    for (int i = 0; i < 16; i++) sP[c*17 + i] = R[i];
    __syncthreads();
    if (c == 0) {
        R[0]=1; R[1]=0; R[2]=0;  R[3]=0;
        R[4]=0; R[5]=1; R[6]=0;  R[7]=0;
        R[8]=0; R[9]=0; R[10]=1; R[11]=0;
        R[12]=0; R[13]=0; R[14]=0; R[15]=1;
    } else {
#pragma unroll
        for (int i = 0; i < 16; i++) R[i] = sP[(c-1)*17 + i];
    }

    // phase C: apply within chunk, rotate v, store
    const float4* __restrict__ Vp =
        (const float4*)(g_v + ((size_t)seq*TLEN + c*CL)*4);
    const int bb = seq >> 4, h = seq & (HEADS - 1);
    const int trow0 = bb*TLEN + c*CL;
#pragma unroll
    for (int t = 0; t < CL; t++) {
        float4 a0 = Op[t*4+0], a1 = Op[t*4+1], a2 = Op[t*4+2], a3 = Op[t*4+3];
        float O[16] = {a0.x,a0.y,a0.z,a0.w, a1.x,a1.y,a1.z,a1.w,
                       a2.x,a2.y,a2.z,a2.w, a3.x,a3.y,a3.z,a3.w};
        float Nn[16];
        mm4(O, R, Nn);
#pragma unroll
        for (int i = 0; i < 16; i++) R[i] = Nn[i];
        float4 vv = Vp[t];
        float r0 = R[0]*vv.x  + R[1]*vv.y  + R[2]*vv.z  + R[3]*vv.w;
        float r1 = R[4]*vv.x  + R[5]*vv.y  + R[6]*vv.z  + R[7]*vv.w;
        float r2 = R[8]*vv.x  + R[9]*vv.y  + R[10]*vv.z + R[11]*vv.w;
        float r3 = R[12]*vv.x + R[13]*vv.y + R[14]*vv.z + R[15]*vv.w;
        *(float4*)(g_rot + (size_t)(trow0 + t)*64 + h*4) = make_float4(r0, r1, r2, r3);
    }
}

// ======================= K6: out = rot @ W_o ==============================
// M=16384, K=64, N=1024. Block 64x128, 256 threads, micro 8x4. K fully in smem.
__global__ __launch_bounds__(256) void k6_gemm_out(
    const float* __restrict__ Wo, float* __restrict__ out)
{
    __shared__ float sa[64][64];     // rot tile  (16 KB)
    __shared__ float sw[64][128];    // W_o tile  (32 KB)

    const int tid = threadIdx.x;
    const int tx  = tid & 31;
    const int ty  = tid >> 5;
    const int m0  = blockIdx.x * 64;
    const int n0  = blockIdx.y * 128;

#pragma unroll
    for (int j = 0; j < 4; j++) {
        int idx4 = tid + j*256;                 // 1024 float4s
        int row = idx4 >> 4, k4 = idx4 & 15;
        *(float4*)&sa[row][k4*4] =
            ((const float4*)(g_rot + (size_t)(m0 + row)*64))[k4];
    }
#pragma unroll
    for (int j = 0; j < 8; j++) {
        int idx4 = tid + j*256;                 // 2048 float4s
        int row = idx4 >> 5, n4 = idx4 & 31;
        *(float4*)&sw[row][n4*4] =
            *(const float4*)(Wo + (size_t)row*DM + n0 + n4*4);
    }
    __syncthreads();

    float acc[8][4];
#pragma unroll
    for (int i = 0; i < 8; i++)
#pragma unroll
        for (int j = 0; j < 4; j++) acc[i][j] = 0.f;

#pragma unroll 8
    for (int k = 0; k < 64; k++) {
        float a[8];
#pragma unroll
        for (int ii = 0; ii < 8; ii++) a[ii] = sa[ty*8 + ii][k];
#pragma unroll
        for (int jj = 0; jj < 4; jj++) {
            float bv = sw[k][tx + jj*32];
#pragma unroll
            for (int ii = 0; ii < 8; ii++) acc[ii][jj] += a[ii]*bv;
        }
    }

#pragma unroll
    for (int ii = 0; ii < 8; ii++) {
        size_t rowoff = (size_t)(m0 + ty*8 + ii)*DM + n0;
#pragma unroll
        for (int jj = 0; jj < 4; jj++)
            out[rowoff + tx + jj*32] = acc[ii][jj];
    }
}

// =========================================================================
extern "C" void kernel_launch(void* const* d_in, const int* in_sizes, int n_in,
                              void* d_out, int out_size)
{
    const float* x   = (const float*)d_in[0];
    const float* Wsk = (const float*)d_in[1];
    const float* Wv  = (const float*)d_in[2];
    const float* Wo  = (const float*)d_in[3];
    float* out = (float*)d_out;

    k1_gemm_in<<<MROWS/64, 256>>>(x, Wsk, Wv);          // 256 blocks
    k2_expm  <<<SEQ*TLEN/256, 256>>>();                  // 1024 blocks
    k345_scan<<<SEQ, NCH>>>();                           // 64 x 512
    k6_gemm_out<<<dim3(MROWS/64, DM/128), 256>>>(Wo, out);
}

// round 8
// speedup vs baseline: 2.3492x; 1.8485x over previous
#include <cuda_runtime.h>
#include <cuda_bf16.h>
#include <math.h>
#include <stdint.h>

#define BATCH 4
#define TLEN  4096
#define DM    1024
#define HEADS 16
#define NSK   6
#define SEQ   (BATCH*HEADS)     // 64
#define MROWS (BATCH*TLEN)      // 16384
#define NQ    160               // 96 skew cols + 64 v cols
#define CL    8                 // scan chunk length
#define NCH   (TLEN/CL)         // 512 chunks per sequence

// ---------------- scratch (static device globals) -------------------------
__device__ __align__(16) float g_skew[SEQ*TLEN*NSK];
__device__ __align__(16) float g_v   [SEQ*TLEN*4];
__device__ __align__(16) float g_O   [SEQ*TLEN*16];
__device__ __align__(16) float g_rot [MROWS*64];
__device__ __align__(16) __nv_bfloat16 g_W1[NQ*DM];   // W^T split hi, [n][k]
__device__ __align__(16) __nv_bfloat16 g_W2[NQ*DM];   // W^T split lo, [n][k]

// ---------------- helpers --------------------------------------------------
__device__ __forceinline__ void mm4(const float* __restrict__ A,
                                    const float* __restrict__ Bm,
                                    float* __restrict__ C) {
#pragma unroll
    for (int i = 0; i < 4; i++)
#pragma unroll
        for (int j = 0; j < 4; j++)
            C[i*4+j] = A[i*4+0]*Bm[0*4+j] + A[i*4+1]*Bm[1*4+j]
                     + A[i*4+2]*Bm[2*4+j] + A[i*4+3]*Bm[3*4+j];
}

__device__ __forceinline__ void mma16816(float* c, const uint32_t* a,
                                         const uint32_t* b) {
    asm volatile(
        "mma.sync.aligned.m16n8k16.row.col.f32.bf16.bf16.f32 "
        "{%0,%1,%2,%3}, {%4,%5,%6,%7}, {%8,%9}, {%0,%1,%2,%3};"
        : "+f"(c[0]), "+f"(c[1]), "+f"(c[2]), "+f"(c[3])
        : "r"(a[0]), "r"(a[1]), "r"(a[2]), "r"(a[3]), "r"(b[0]), "r"(b[1]));
}

// ======================= K0: split W into 2 bf16 terms (transposed) =======
__global__ __launch_bounds__(256) void k0_wsplit(
    const float* __restrict__ Wsk, const float* __restrict__ Wv)
{
    int idx = blockIdx.x*256 + threadIdx.x;     // 0 .. NQ*DM-1
    int k = idx / NQ;
    int n = idx - k*NQ;
    float w = (n < 96) ? Wsk[(size_t)k*96 + n] : Wv[(size_t)k*64 + (n - 96)];
    __nv_bfloat16 h1 = __float2bfloat16(w);
    float r1 = w - __bfloat162float(h1);
    __nv_bfloat16 h2 = __float2bfloat16(r1);
    size_t o = (size_t)n*DM + k;
    g_W1[o] = h1; g_W2[o] = h2;
}

// ======================= K1: mma.sync bf16 split GEMM =====================
// G = x @ [W_skew | W_v], M=16384, K=1024, N=160.
// x=x1+x2, W=w1+w2 (bf16); C ~= x1w1 + x1w2 + x2w1  (err ~2^-18 per entry).
// CTA: 128 rows x 160 cols, 256 thr (8 warps: 4M x 2N), warp tile 32x80.
// KC=32, STATIC shared (46080 B < 48KB): no attribute calls, no dyn smem.
#define KC    32                 // k per chunk
#define ASTR  40                 // bf16 row stride (pad 8) -> conflict-free

__global__ __launch_bounds__(256) void k1_mma(const float* __restrict__ x)
{
    __shared__ __nv_bfloat16 sA1[128*ASTR];   // 10240 B
    __shared__ __nv_bfloat16 sA2[128*ASTR];   // 10240 B
    __shared__ __nv_bfloat16 sB1[NQ*ASTR];    // 12800 B
    __shared__ __nv_bfloat16 sB2[NQ*ASTR];    // 12800 B

    const int tid  = threadIdx.x;
    const int lane = tid & 31;
    const int wrp  = tid >> 5;          // 0..7
    const int wm   = wrp >> 1;          // 0..3  (M groups of 32)
    const int wn   = wrp & 1;           // 0..1  (N groups of 80)
    const int m0   = blockIdx.x * 128;

    float acc[2][10][4];
#pragma unroll
    for (int i = 0; i < 2; i++)
#pragma unroll
        for (int j = 0; j < 10; j++)
#pragma unroll
            for (int q = 0; q < 4; q++) acc[i][j][q] = 0.f;

    for (int ch = 0; ch < DM/KC; ch++) {
        const int k0 = ch * KC;
        // ---- load + split x tile: 128 rows x 32 k (1024 float4) ----
#pragma unroll
        for (int i = 0; i < 4; i++) {
            int idx4 = tid + i*256;
            int row = idx4 >> 3, c4 = idx4 & 7;
            float4 xv = *(const float4*)(x + (size_t)(m0 + row)*DM + k0 + c4*4);
            float vf[4] = {xv.x, xv.y, xv.z, xv.w};
            __nv_bfloat16 hi[4], lo[4];
#pragma unroll
            for (int j = 0; j < 4; j++) {
                hi[j] = __float2bfloat16(vf[j]);
                lo[j] = __float2bfloat16(vf[j] - __bfloat162float(hi[j]));
            }
            int so = row*ASTR + c4*4;
            __nv_bfloat162 p0 = __halves2bfloat162(hi[0], hi[1]);
            __nv_bfloat162 p1 = __halves2bfloat162(hi[2], hi[3]);
            uint2 pu; pu.x = *(uint32_t*)&p0; pu.y = *(uint32_t*)&p1;
            *(uint2*)(sA1 + so) = pu;
            p0 = __halves2bfloat162(lo[0], lo[1]);
            p1 = __halves2bfloat162(lo[2], lo[3]);
            pu.x = *(uint32_t*)&p0; pu.y = *(uint32_t*)&p1;
            *(uint2*)(sA2 + so) = pu;
        }
        // ---- load W tiles (bf16, [n][k]): 160 rows x 32 k (1280 uint2) ----
#pragma unroll
        for (int i = 0; i < 5; i++) {
            int idx2 = tid + i*256;
            int n = idx2 >> 3, c2 = idx2 & 7;
            size_t ga = (size_t)n*DM + k0 + c2*4;
            int so = n*ASTR + c2*4;
            *(uint2*)(sB1 + so) = *(const uint2*)(g_W1 + ga);
            *(uint2*)(sB2 + so) = *(const uint2*)(g_W2 + ga);
        }
        __syncthreads();

        // ---- 2 k16 steps ----
#pragma unroll
        for (int ks = 0; ks < 2; ks++) {
            const int kb = ks*16 + (lane & 3)*2;
            uint32_t a1f[2][4], a2f[2][4];
#pragma unroll
            for (int im = 0; im < 2; im++) {
                int r0 = (wm*32 + im*16 + (lane >> 2))*ASTR + kb;
                a1f[im][0] = *(uint32_t*)(sA1 + r0);
                a1f[im][1] = *(uint32_t*)(sA1 + r0 + 8*ASTR);
                a1f[im][2] = *(uint32_t*)(sA1 + r0 + 8);
                a1f[im][3] = *(uint32_t*)(sA1 + r0 + 8*ASTR + 8);
                a2f[im][0] = *(uint32_t*)(sA2 + r0);
                a2f[im][1] = *(uint32_t*)(sA2 + r0 + 8*ASTR);
                a2f[im][2] = *(uint32_t*)(sA2 + r0 + 8);
                a2f[im][3] = *(uint32_t*)(sA2 + r0 + 8*ASTR + 8);
            }
#pragma unroll
            for (int in = 0; in < 10; in++) {
                int nb = (wn*80 + in*8 + (lane >> 2))*ASTR + kb;
                uint32_t b1f[2], b2f[2];
                b1f[0] = *(uint32_t*)(sB1 + nb);
                b1f[1] = *(uint32_t*)(sB1 + nb + 8);
                b2f[0] = *(uint32_t*)(sB2 + nb);
                b2f[1] = *(uint32_t*)(sB2 + nb + 8);
#pragma unroll
                for (int im = 0; im < 2; im++) {
                    mma16816(acc[im][in], a1f[im], b1f);   // x1*w1
                    mma16816(acc[im][in], a1f[im], b2f);   // x1*w2
                    mma16816(acc[im][in], a2f[im], b1f);   // x2*w1
                }
            }
        }
        __syncthreads();
    }

    // ---- epilogue: scatter fp32 to seq-major layouts ----
#pragma unroll
    for (int im = 0; im < 2; im++) {
        int rbase = m0 + wm*32 + im*16 + (lane >> 2);
#pragma unroll
        for (int half = 0; half < 2; half++) {
            int m  = rbase + half*8;
            int bb = m >> 12;
            int t  = m & (TLEN - 1);
#pragma unroll
            for (int in = 0; in < 10; in++) {
                int col = wn*80 + in*8 + (lane & 3)*2;
#pragma unroll
                for (int q = 0; q < 2; q++) {
                    int n = col + q;
                    float vv = acc[im][in][half*2 + q];
                    if (n < 96) {
                        int h = n / 6, kk = n - h*6;
                        g_skew[((size_t)(bb*HEADS + h)*TLEN + t)*NSK + kk] = vv;
                    } else {
                        int i2 = n - 96;
                        int h = i2 >> 2, cc = i2 & 3;
                        g_v[((size_t)(bb*HEADS + h)*TLEN + t)*4 + cc] = vv;
                    }
                }
            }
        }
    }
}

// ======================= K2: O_t = expm(skew) =============================
__global__ __launch_bounds__(256) void k2_expm()
{
    int u = blockIdx.x * 256 + threadIdx.x;
    const float* s = g_skew + (size_t)u * NSK;
    float a = s[0], b = s[1], c = s[2], d = s[3], e = s[4], f = s[5];

    float nrm = sqrtf(2.f*(a*a + b*b + c*c + d*d + e*e + f*f));
    int sh = 0;
    if (nrm > 0.5f) {
        sh = (int)ceilf(log2f(nrm)) + 1;
        if (sh < 1) sh = 1;
    }
    float sc = exp2f(-(float)sh);
    a *= sc; b *= sc; c *= sc; d *= sc; e *= sc; f *= sc;

    float Y[16] = { 0,  a,  b,  c,
                   -a,  0,  d,  e,
                   -b, -d,  0,  f,
                   -c, -e, -f,  0};
    float Mt[16];
#pragma unroll
    for (int i = 0; i < 16; i++) Mt[i] = Y[i] * (1.f/9.f);
    Mt[0] += 1.f; Mt[5] += 1.f; Mt[10] += 1.f; Mt[15] += 1.f;
#pragma unroll
    for (int j = 8; j >= 1; j--) {
        float Tt[16];
        mm4(Y, Mt, Tt);
        float inv = 1.f / (float)j;
#pragma unroll
        for (int i = 0; i < 16; i++) Mt[i] = Tt[i] * inv;
        Mt[0] += 1.f; Mt[5] += 1.f; Mt[10] += 1.f; Mt[15] += 1.f;
    }
    for (int q = 0; q < sh; q++) {
        float Tt[16];
        mm4(Mt, Mt, Tt);
#pragma unroll
        for (int i = 0; i < 16; i++) Mt[i] = Tt[i];
    }
    float4* o = (float4*)(g_O + (size_t)u * 16);
    o[0] = make_float4(Mt[0],  Mt[1],  Mt[2],  Mt[3]);
    o[1] = make_float4(Mt[4],  Mt[5],  Mt[6],  Mt[7]);
    o[2] = make_float4(Mt[8],  Mt[9],  Mt[10], Mt[11]);
    o[3] = make_float4(Mt[12], Mt[13], Mt[14], Mt[15]);
}

// =========== K345: fused chunk product + Kogge-Stone scan + apply =========
__global__ __launch_bounds__(512) void k345_scan()
{
    __shared__ float sP[NCH*17];
    const int seq = blockIdx.x;
    const int c   = threadIdx.x;            // chunk id 0..511
    const float4* __restrict__ Op =
        (const float4*)(g_O + ((size_t)seq*TLEN + c*CL)*16);

    float R[16];
    {
        float4 a0 = Op[0], a1 = Op[1], a2 = Op[2], a3 = Op[3];
        R[0]=a0.x; R[1]=a0.y; R[2]=a0.z; R[3]=a0.w;
        R[4]=a1.x; R[5]=a1.y; R[6]=a1.z; R[7]=a1.w;
        R[8]=a2.x; R[9]=a2.y; R[10]=a2.z; R[11]=a2.w;
        R[12]=a3.x; R[13]=a3.y; R[14]=a3.z; R[15]=a3.w;
    }
#pragma unroll
    for (int t = 1; t < CL; t++) {
        float4 a0 = Op[t*4+0], a1 = Op[t*4+1], a2 = Op[t*4+2], a3 = Op[t*4+3];
        float O[16] = {a0.x,a0.y,a0.z,a0.w, a1.x,a1.y,a1.z,a1.w,
                       a2.x,a2.y,a2.z,a2.w, a3.x,a3.y,a3.z,a3.w};
        float Nn[16];
        mm4(O, R, Nn);
#pragma unroll
        for (int i = 0; i < 16; i++) R[i] = Nn[i];
    }

    for (int d = 1; d < NCH; d <<= 1) {
#pragma unroll
        for (int i = 0; i < 16; i++) sP[c*17 + i] = R[i];
        __syncthreads();
        if (c >= d) {
            float Q[16];
#pragma unroll
            for (int i = 0; i < 16; i++) Q[i] = sP[(c-d)*17 + i];
            float Nn[16];
            mm4(R, Q, Nn);
#pragma unroll
            for (int i = 0; i < 16; i++) R[i] = Nn[i];
        }
        __syncthreads();
    }
#pragma unroll
    for (int i = 0; i < 16; i++) sP[c*17 + i] = R[i];
    __syncthreads();
    if (c == 0) {
        R[0]=1; R[1]=0; R[2]=0;  R[3]=0;
        R[4]=0; R[5]=1; R[6]=0;  R[7]=0;
        R[8]=0; R[9]=0; R[10]=1; R[11]=0;
        R[12]=0; R[13]=0; R[14]=0; R[15]=1;
    } else {
#pragma unroll
        for (int i = 0; i < 16; i++) R[i] = sP[(c-1)*17 + i];
    }

    const float4* __restrict__ Vp =
        (const float4*)(g_v + ((size_t)seq*TLEN + c*CL)*4);
    const int bb = seq >> 4, h = seq & (HEADS - 1);
    const int trow0 = bb*TLEN + c*CL;
#pragma unroll
    for (int t = 0; t < CL; t++) {
        float4 a0 = Op[t*4+0], a1 = Op[t*4+1], a2 = Op[t*4+2], a3 = Op[t*4+3];
        float O[16] = {a0.x,a0.y,a0.z,a0.w, a1.x,a1.y,a1.z,a1.w,
                       a2.x,a2.y,a2.z,a2.w, a3.x,a3.y,a3.z,a3.w};
        float Nn[16];
        mm4(O, R, Nn);
#pragma unroll
        for (int i = 0; i < 16; i++) R[i] = Nn[i];
        float4 vv = Vp[t];
        float r0 = R[0]*vv.x  + R[1]*vv.y  + R[2]*vv.z  + R[3]*vv.w;
        float r1 = R[4]*vv.x  + R[5]*vv.y  + R[6]*vv.z  + R[7]*vv.w;
        float r2 = R[8]*vv.x  + R[9]*vv.y  + R[10]*vv.z + R[11]*vv.w;
        float r3 = R[12]*vv.x + R[13]*vv.y + R[14]*vv.z + R[15]*vv.w;
        *(float4*)(g_rot + (size_t)(trow0 + t)*64 + h*4) = make_float4(r0, r1, r2, r3);
    }
}

// ======================= K6: out = rot @ W_o (fp32) =======================
__global__ __launch_bounds__(256) void k6_gemm_out(
    const float* __restrict__ Wo, float* __restrict__ out)
{
    __shared__ float sa[64][64];
    __shared__ float sw[64][128];

    const int tid = threadIdx.x;
    const int tx  = tid & 31;
    const int ty  = tid >> 5;
    const int m0  = blockIdx.x * 64;
    const int n0  = blockIdx.y * 128;

#pragma unroll
    for (int j = 0; j < 4; j++) {
        int idx4 = tid + j*256;
        int row = idx4 >> 4, k4 = idx4 & 15;
        *(float4*)&sa[row][k4*4] =
            ((const float4*)(g_rot + (size_t)(m0 + row)*64))[k4];
    }
#pragma unroll
    for (int j = 0; j < 8; j++) {
        int idx4 = tid + j*256;
        int row = idx4 >> 5, n4 = idx4 & 31;
        *(float4*)&sw[row][n4*4] =
            *(const float4*)(Wo + (size_t)row*DM + n0 + n4*4);
    }
    __syncthreads();

    float acc[8][4];
#pragma unroll
    for (int i = 0; i < 8; i++)
#pragma unroll
        for (int j = 0; j < 4; j++) acc[i][j] = 0.f;

#pragma unroll 8
    for (int k = 0; k < 64; k++) {
        float a[8];
#pragma unroll
        for (int ii = 0; ii < 8; ii++) a[ii] = sa[ty*8 + ii][k];
#pragma unroll
        for (int jj = 0; jj < 4; jj++) {
            float bv = sw[k][tx + jj*32];
#pragma unroll
            for (int ii = 0; ii < 8; ii++) acc[ii][jj] += a[ii]*bv;
        }
    }

#pragma unroll
    for (int ii = 0; ii < 8; ii++) {
        size_t rowoff = (size_t)(m0 + ty*8 + ii)*DM + n0;
#pragma unroll
        for (int jj = 0; jj < 4; jj++)
            out[rowoff + tx + jj*32] = acc[ii][jj];
    }
}

// =========================================================================
extern "C" void kernel_launch(void* const* d_in, const int* in_sizes, int n_in,
                              void* d_out, int out_size)
{
    const float* x   = (const float*)d_in[0];
    const float* Wsk = (const float*)d_in[1];
    const float* Wv  = (const float*)d_in[2];
    const float* Wo  = (const float*)d_in[3];
    float* out = (float*)d_out;

    k0_wsplit<<<NQ*DM/256, 256>>>(Wsk, Wv);              // 640 blocks
    k1_mma  <<<MROWS/128, 256>>>(x);                     // 128 CTAs, HMMA
    k2_expm <<<SEQ*TLEN/256, 256>>>();                   // 1024 blocks
    k345_scan<<<SEQ, NCH>>>();                           // 64 x 512
    k6_gemm_out<<<dim3(MROWS/64, DM/128), 256>>>(Wo, out);
}